// round 5
// baseline (speedup 1.0000x reference)
#include <cuda_runtime.h>

#define BH_ 16

// gmem scratch
__device__ float g_xs[BH_ * 128 * 32];   // softmaxed x, stride 32
__device__ float g_sv[BH_ * 128 * 34];   // sorted values, stride 34 (8B-align for LDS.64)
__device__ float g_qA[BH_ * 128 * 33];   // suffix sum of v   (coeff of 0.5 u^2)
__device__ float g_qB[BH_ * 128 * 33];   // 0.5 prefix v^2    (coeff of u)
__device__ float g_qC[BH_ * 128 * 33];   // -prefix v^3 / 6   (constant)
__device__ float g_lg[BH_ * 128 * 128];  // raw logits
__device__ float g_o [BH_ * 128 * 32];   // attn @ x

static const int SMEM_PROJ = (8 * 256 + 32 * 257 + 8 * 32) * 4;              // 42112
static const int SMEM_SPL  = (128 * 34 + 3 * 128 * 33 + 128 * 32) * 4;       // 84480
static const int SMEM_AV   = (128 * 32 + 8 * 128) * 4;                       // 20480
static const int SMEM_OUT  = SMEM_PROJ;

__device__ __forceinline__ float wmax(float v) {
    #pragma unroll
    for (int o = 16; o > 0; o >>= 1) v = fmaxf(v, __shfl_xor_sync(0xffffffffu, v, o));
    return v;
}
__device__ __forceinline__ float wsum(float v) {
    #pragma unroll
    for (int o = 16; o > 0; o >>= 1) v += __shfl_xor_sync(0xffffffffu, v, o);
    return v;
}
__device__ __forceinline__ float bitonic32(float v, int l) {
    #pragma unroll
    for (int k = 2; k <= 32; k <<= 1) {
        #pragma unroll
        for (int j = k >> 1; j > 0; j >>= 1) {
            const float o = __shfl_xor_sync(0xffffffffu, v, j);
            const bool up = ((l & k) == 0);
            const bool lower = ((l & j) == 0);
            v = (lower == up) ? fminf(v, o) : fmaxf(v, o);
        }
    }
    return v;
}
__device__ __forceinline__ float iscan(float x, int l) {
    #pragma unroll
    for (int o = 1; o < 32; o <<= 1) {
        const float n = __shfl_up_sync(0xffffffffu, x, o);
        if (l >= o) x += n;
    }
    return x;
}

// ---------------------------------------------------------------------------
// K1: in-proj GEMM (8 rows x 32 cols, K-split x2) + softmax + sort + tables.
// grid(32,8), 256 thr.
// ---------------------------------------------------------------------------
__global__ void k_proj(const float* __restrict__ inp,
                       const float* __restrict__ w_in,
                       const float* __restrict__ b_in) {
    extern __shared__ float sm[];
    float* xs = sm;                 // [8][256]
    float* ws = sm + 8 * 256;       // [32][257]
    float* ps = ws + 32 * 257;      // [8][32]

    const int t = threadIdx.x, lane = t & 31, wid = t >> 5;
    const int r0 = blockIdx.x * 8, hd = blockIdx.y, c0 = hd * 32;

    #pragma unroll
    for (int f = t; f < 512; f += 256) {
        const int r = f >> 6, kq = f & 63;
        *(float4*)(xs + r * 256 + kq * 4) = *(const float4*)(inp + (r0 + r) * 256 + kq * 4);
    }
    #pragma unroll
    for (int rr = 0; rr < 4; ++rr) {
        const int cc = wid * 4 + rr;
        #pragma unroll
        for (int hh = 0; hh < 2; ++hh) {
            const int k4 = hh * 32 + lane;
            const float4 v = *(const float4*)(w_in + (c0 + cc) * 256 + k4 * 4);
            float* d = ws + cc * 257 + k4 * 4;
            d[0] = v.x; d[1] = v.y; d[2] = v.z; d[3] = v.w;
        }
    }
    __syncthreads();

    const int kh = wid >> 2, rg = wid & 3;
    const float* wrow = ws + lane * 257 + kh * 128;
    float acc[2] = {0.f, 0.f};
    #pragma unroll 8
    for (int kq = 0; kq < 32; ++kq) {
        const float w0 = wrow[4 * kq + 0], w1 = wrow[4 * kq + 1];
        const float w2 = wrow[4 * kq + 2], w3 = wrow[4 * kq + 3];
        #pragma unroll
        for (int rr = 0; rr < 2; ++rr) {
            const float4 x4 = *(const float4*)(xs + (rg * 2 + rr) * 256 + kh * 128 + 4 * kq);
            acc[rr] = fmaf(w0, x4.x, fmaf(w1, x4.y, fmaf(w2, x4.z, fmaf(w3, x4.w, acc[rr]))));
        }
    }
    if (kh == 1) {
        #pragma unroll
        for (int rr = 0; rr < 2; ++rr) ps[(rg * 2 + rr) * 32 + lane] = acc[rr];
    }
    __syncthreads();
    if (kh == 0) {
        const float bb = b_in[c0 + lane];
        #pragma unroll
        for (int rr = 0; rr < 2; ++rr) {
            const float val = acc[rr] + ps[(rg * 2 + rr) * 32 + lane] + bb;
            const float mx = wmax(val);
            float p = __expf(val - mx);
            const float smv = wsum(p);
            p = p / smv;

            const int row = r0 + rg * 2 + rr;
            const int b = row >> 7, s = row & 127;
            const int rowo = (b * 8 + hd) * 128 + s;
            g_xs[rowo * 32 + lane] = p;

            const float v  = bitonic32(p, lane);
            g_sv[rowo * 34 + lane] = v;
            const float v2 = v * v, v3 = v2 * v;
            const float s1 = iscan(v, lane);
            const float s2 = iscan(v2, lane);
            const float s3 = iscan(v3, lane);
            const float T1 = __shfl_sync(0xffffffffu, s1, 31);

            g_qA[rowo * 33 + lane] = T1 - (s1 - v);
            g_qB[rowo * 33 + lane] = 0.5f * (s2 - v2);
            g_qC[rowo * 33 + lane] = -(s3 - v3) * (1.f / 6.f);
            if (lane == 31) {
                g_qA[rowo * 33 + 32] = 0.f;
                g_qB[rowo * 33 + 32] = 0.5f * s2;
                g_qC[rowo * 33 + 32] = -s3 * (1.f / 6.f);
            }
        }
    }
}

// ---------------------------------------------------------------------------
// K2a: spline logits. Warp owns rows i and 127-i (exactly 129 j-evals total),
// j >= i only, mirrored writes. grid(8, 16), 256 thr. lane = e.
// ---------------------------------------------------------------------------
__global__ void k_spline() {
    extern __shared__ float sm[];
    float* sv  = sm;                 // [128][34]
    float* qA  = sv + 128 * 34;      // [128][33]
    float* qB  = qA + 128 * 33;
    float* qC  = qB + 128 * 33;
    float* xsh = qC + 128 * 33;      // [128][32]

    const int t = threadIdx.x, lane = t & 31, wid = t >> 5;
    const int bh = blockIdx.y;

    for (int f = t; f < 1088; f += 256)
        *(float4*)(sv + 4 * f) = *(const float4*)(g_sv + bh * 4352 + 4 * f);
    for (int f = t; f < 1056; f += 256) {
        *(float4*)(qA + 4 * f) = *(const float4*)(g_qA + bh * 4224 + 4 * f);
        *(float4*)(qB + 4 * f) = *(const float4*)(g_qB + bh * 4224 + 4 * f);
        *(float4*)(qC + 4 * f) = *(const float4*)(g_qC + bh * 4224 + 4 * f);
    }
    for (int f = t; f < 1024; f += 256)
        *(float4*)(xsh + 4 * f) = *(const float4*)(g_xs + bh * 4096 + 4 * f);
    __syncthreads();

    float* LG = g_lg + bh * 16384;
    const int ibase = blockIdx.x * 8 + wid;   // 0..63

    #pragma unroll
    for (int half = 0; half < 2; ++half) {
        const int i = half ? (127 - ibase) : ibase;
        const float u  = xsh[i * 32 + lane];
        const float u2 = 0.5f * u * u;
        const float u3 = u * u * u * (1.f / 6.f);

        #pragma unroll 4
        for (int j = i; j < 128; ++j) {
            const float* svj = sv + j * 34;
            int r = (svj[15] < u) ? 16 : 0;
            r += (svj[r + 7] < u) ? 8 : 0;
            r += (svj[r + 3] < u) ? 4 : 0;
            r += (svj[r + 1] < u) ? 2 : 0;
            const float2 pr = *(const float2*)(svj + r);   // 8B aligned (stride 34, r even)
            r += (pr.x < u) ? 1 : 0;
            r += (pr.y < u) ? 1 : 0;
            const int o = j * 33 + r;
            float val = fmaf(u2, qA[o], fmaf(u, qB[o], fmaf(u3, (float)r, qC[o])));
            val = wsum(val);
            if (lane == 0) {
                LG[i * 128 + j] = val;
                if (j > i) LG[j * 128 + i] = val;
            }
        }
    }
}

// ---------------------------------------------------------------------------
// K2b: per-row softmax over j + out = attn @ x. grid(16,16), 256 thr.
// ---------------------------------------------------------------------------
__global__ void k_attn_av() {
    extern __shared__ float sm[];
    float* xsh  = sm;            // [128][32]
    float* attn = sm + 4096;     // [8][128]

    const int t = threadIdx.x, lane = t & 31, wid = t >> 5;
    const int bh = blockIdx.y, i = blockIdx.x * 8 + wid;

    for (int f = t; f < 1024; f += 256)
        *(float4*)(xsh + 4 * f) = *(const float4*)(g_xs + bh * 4096 + 4 * f);
    __syncthreads();

    const float4 lg4 = *(const float4*)(g_lg + bh * 16384 + i * 128 + lane * 4);
    const float l0 = lg4.x * (1.f / 32.f), l1 = lg4.y * (1.f / 32.f);
    const float l2 = lg4.z * (1.f / 32.f), l3 = lg4.w * (1.f / 32.f);
    float mx = fmaxf(fmaxf(l0, l1), fmaxf(l2, l3));
    mx = wmax(mx);
    const float e0 = __expf(l0 - mx), e1 = __expf(l1 - mx);
    const float e2 = __expf(l2 - mx), e3 = __expf(l3 - mx);
    float s = (e0 + e1) + (e2 + e3);
    s = wsum(s);
    const float inv = 1.f / s;
    float* at = attn + wid * 128;
    *(float4*)(at + lane * 4) = make_float4(e0 * inv, e1 * inv, e2 * inv, e3 * inv);
    __syncwarp();

    float a0 = 0.f, a1 = 0.f;
    #pragma unroll 8
    for (int j = 0; j < 128; j += 2) {
        a0 = fmaf(at[j],     xsh[j * 32 + lane],       a0);
        a1 = fmaf(at[j + 1], xsh[(j + 1) * 32 + lane], a1);
    }
    g_o[(bh * 128 + i) * 32 + lane] = a0 + a1;
}

// ---------------------------------------------------------------------------
// K3: out = o @ w_out^T + b_out. 8-row tiles, K-split x2. grid(32,8), 256 thr.
// ---------------------------------------------------------------------------
__global__ void k_out(const float* __restrict__ w_out,
                      const float* __restrict__ b_out,
                      float* __restrict__ out) {
    extern __shared__ float sm[];
    float* xs = sm;
    float* ws = sm + 8 * 256;
    float* ps = ws + 32 * 257;

    const int t = threadIdx.x, lane = t & 31, wid = t >> 5;
    const int r0 = blockIdx.x * 8, c0 = blockIdx.y * 32;

    #pragma unroll
    for (int f = t; f < 512; f += 256) {
        const int r = f >> 6, kq = f & 63;
        const int row = r0 + r, b = row >> 7, s = row & 127;
        const int d = kq * 4, h = d >> 5, e = d & 31;
        *(float4*)(xs + r * 256 + kq * 4) =
            *(const float4*)(g_o + ((b * 8 + h) * 128 + s) * 32 + e);
    }
    #pragma unroll
    for (int rr = 0; rr < 4; ++rr) {
        const int cc = wid * 4 + rr;
        #pragma unroll
        for (int hh = 0; hh < 2; ++hh) {
            const int k4 = hh * 32 + lane;
            const float4 v = *(const float4*)(w_out + (c0 + cc) * 256 + k4 * 4);
            float* d = ws + cc * 257 + k4 * 4;
            d[0] = v.x; d[1] = v.y; d[2] = v.z; d[3] = v.w;
        }
    }
    __syncthreads();

    const int kh = wid >> 2, rg = wid & 3;
    const float* wrow = ws + lane * 257 + kh * 128;
    float acc[2] = {0.f, 0.f};
    #pragma unroll 8
    for (int kq = 0; kq < 32; ++kq) {
        const float w0 = wrow[4 * kq + 0], w1 = wrow[4 * kq + 1];
        const float w2 = wrow[4 * kq + 2], w3 = wrow[4 * kq + 3];
        #pragma unroll
        for (int rr = 0; rr < 2; ++rr) {
            const float4 x4 = *(const float4*)(xs + (rg * 2 + rr) * 256 + kh * 128 + 4 * kq);
            acc[rr] = fmaf(w0, x4.x, fmaf(w1, x4.y, fmaf(w2, x4.z, fmaf(w3, x4.w, acc[rr]))));
        }
    }
    if (kh == 1) {
        #pragma unroll
        for (int rr = 0; rr < 2; ++rr) ps[(rg * 2 + rr) * 32 + lane] = acc[rr];
    }
    __syncthreads();
    if (kh == 0) {
        const float bb = b_out[c0 + lane];
        #pragma unroll
        for (int rr = 0; rr < 2; ++rr)
            out[(r0 + rg * 2 + rr) * 256 + c0 + lane] =
                acc[rr] + ps[(rg * 2 + rr) * 32 + lane] + bb;
    }
}

extern "C" void kernel_launch(void* const* d_in, const int* in_sizes, int n_in,
                              void* d_out, int out_size) {
    const float* inp   = (const float*)d_in[0];
    const float* w_in  = (const float*)d_in[1];
    const float* b_in  = (const float*)d_in[2];
    const float* w_out = (const float*)d_in[3];
    const float* b_out = (const float*)d_in[4];
    float* out = (float*)d_out;
    (void)in_sizes; (void)n_in; (void)out_size;

    cudaFuncSetAttribute(k_proj,    cudaFuncAttributeMaxDynamicSharedMemorySize, SMEM_PROJ);
    cudaFuncSetAttribute(k_spline,  cudaFuncAttributeMaxDynamicSharedMemorySize, SMEM_SPL);
    cudaFuncSetAttribute(k_attn_av, cudaFuncAttributeMaxDynamicSharedMemorySize, SMEM_AV);
    cudaFuncSetAttribute(k_out,     cudaFuncAttributeMaxDynamicSharedMemorySize, SMEM_OUT);

    k_proj   <<<dim3(32, 8),  256, SMEM_PROJ>>>(inp, w_in, b_in);
    k_spline <<<dim3(8, 16),  256, SMEM_SPL>>>();
    k_attn_av<<<dim3(16, 16), 256, SMEM_AV>>>();
    k_out    <<<dim3(32, 8),  256, SMEM_OUT>>>(w_out, b_out, out);
}

// round 6
// speedup vs baseline: 1.3685x; 1.3685x over previous
#include <cuda_runtime.h>

#define BH_ 16

// gmem scratch
__device__ float  g_xs[BH_ * 128 * 32];    // softmaxed x, stride 32
__device__ float  g_sv[BH_ * 128 * 34];    // sorted values, stride 34 (LDS.64 align)
__device__ float4 g_q4[BH_ * 128 * 33];    // rank table: (qA, qB, qC, r)
__device__ float  g_o [BH_ * 128 * 32];    // attn @ x

static const int SMEM_PROJ = (8 * 256 + 32 * 257 + 8 * 32) * 4;  // 42112
static const int SMEM_SPL  = 128 * 33 * 16                        // q4
                           + (128 * 34 + 128 * 32) * 4            // sv + xsh
                           + 16 * 128 * 4;                        // attn rows  = 109568
static const int SMEM_OUT  = SMEM_PROJ;

__device__ __forceinline__ float wmax(float v) {
    #pragma unroll
    for (int o = 16; o > 0; o >>= 1) v = fmaxf(v, __shfl_xor_sync(0xffffffffu, v, o));
    return v;
}
__device__ __forceinline__ float wsum(float v) {
    #pragma unroll
    for (int o = 16; o > 0; o >>= 1) v += __shfl_xor_sync(0xffffffffu, v, o);
    return v;
}
__device__ __forceinline__ float bitonic32(float v, int l) {
    #pragma unroll
    for (int k = 2; k <= 32; k <<= 1) {
        #pragma unroll
        for (int j = k >> 1; j > 0; j >>= 1) {
            const float o = __shfl_xor_sync(0xffffffffu, v, j);
            const bool up = ((l & k) == 0);
            const bool lower = ((l & j) == 0);
            v = (lower == up) ? fminf(v, o) : fmaxf(v, o);
        }
    }
    return v;
}
__device__ __forceinline__ float iscan(float x, int l) {
    #pragma unroll
    for (int o = 1; o < 32; o >>= 0 ? o <<= 1, 0 : 0) { }  // (unused stub guard)
    return x;
}
__device__ __forceinline__ float iscan2(float x, int l) {
    #pragma unroll
    for (int o = 1; o < 32; o <<= 1) {
        const float n = __shfl_up_sync(0xffffffffu, x, o);
        if (l >= o) x += n;
    }
    return x;
}

// ---------------------------------------------------------------------------
// K1: in-proj GEMM (8 rows x 32 cols, K-split x2) + softmax + sort + table.
// grid(32,8), 256 thr.
// ---------------------------------------------------------------------------
__global__ void k_proj(const float* __restrict__ inp,
                       const float* __restrict__ w_in,
                       const float* __restrict__ b_in) {
    extern __shared__ float sm[];
    float* xs = sm;                 // [8][256]
    float* ws = sm + 8 * 256;       // [32][257]
    float* ps = ws + 32 * 257;      // [8][32]

    const int t = threadIdx.x, lane = t & 31, wid = t >> 5;
    const int r0 = blockIdx.x * 8, hd = blockIdx.y, c0 = hd * 32;

    #pragma unroll
    for (int f = t; f < 512; f += 256) {
        const int r = f >> 6, kq = f & 63;
        *(float4*)(xs + r * 256 + kq * 4) = *(const float4*)(inp + (r0 + r) * 256 + kq * 4);
    }
    #pragma unroll
    for (int rr = 0; rr < 4; ++rr) {
        const int cc = wid * 4 + rr;
        #pragma unroll
        for (int hh = 0; hh < 2; ++hh) {
            const int k4 = hh * 32 + lane;
            const float4 v = *(const float4*)(w_in + (c0 + cc) * 256 + k4 * 4);
            float* d = ws + cc * 257 + k4 * 4;
            d[0] = v.x; d[1] = v.y; d[2] = v.z; d[3] = v.w;
        }
    }
    __syncthreads();

    const int kh = wid >> 2, rg = wid & 3;
    const float* wrow = ws + lane * 257 + kh * 128;
    float acc[2] = {0.f, 0.f};
    #pragma unroll 8
    for (int kq = 0; kq < 32; ++kq) {
        const float w0 = wrow[4 * kq + 0], w1 = wrow[4 * kq + 1];
        const float w2 = wrow[4 * kq + 2], w3 = wrow[4 * kq + 3];
        #pragma unroll
        for (int rr = 0; rr < 2; ++rr) {
            const float4 x4 = *(const float4*)(xs + (rg * 2 + rr) * 256 + kh * 128 + 4 * kq);
            acc[rr] = fmaf(w0, x4.x, fmaf(w1, x4.y, fmaf(w2, x4.z, fmaf(w3, x4.w, acc[rr]))));
        }
    }
    if (kh == 1) {
        #pragma unroll
        for (int rr = 0; rr < 2; ++rr) ps[(rg * 2 + rr) * 32 + lane] = acc[rr];
    }
    __syncthreads();
    if (kh == 0) {
        const float bb = b_in[c0 + lane];
        #pragma unroll
        for (int rr = 0; rr < 2; ++rr) {
            const float val = acc[rr] + ps[(rg * 2 + rr) * 32 + lane] + bb;
            const float mx = wmax(val);
            float p = __expf(val - mx);
            const float smv = wsum(p);
            p = p / smv;

            const int row = r0 + rg * 2 + rr;
            const int b = row >> 7, s = row & 127;
            const int rowo = (b * 8 + hd) * 128 + s;
            g_xs[rowo * 32 + lane] = p;

            const float v  = bitonic32(p, lane);
            g_sv[rowo * 34 + lane] = v;
            const float v2 = v * v, v3 = v2 * v;
            const float s1 = iscan2(v, lane);
            const float s2 = iscan2(v2, lane);
            const float s3 = iscan2(v3, lane);
            const float T1 = __shfl_sync(0xffffffffu, s1, 31);

            g_q4[rowo * 33 + lane] = make_float4(
                T1 - (s1 - v), 0.5f * (s2 - v2), -(s3 - v3) * (1.f / 6.f), (float)lane);
            if (lane == 31)
                g_q4[rowo * 33 + 32] = make_float4(
                    0.f, 0.5f * s2, -s3 * (1.f / 6.f), 32.f);
        }
    }
}

// ---------------------------------------------------------------------------
// K2: fused spline logits + row softmax + AV. grid(8, 16), 512 thr (16 warps).
// Warp wid owns full row i = bx*16 + wid; lane = e.
// ---------------------------------------------------------------------------
__global__ void __launch_bounds__(512) k_spline() {
    extern __shared__ float sm_raw[];
    float4* q4  = (float4*)sm_raw;                  // [128*33]
    float*  sv  = (float*)(q4 + 128 * 33);          // [128*34]
    float*  xsh = sv + 128 * 34;                    // [128*32]
    float*  attn = xsh + 128 * 32;                  // [16][128]

    const int t = threadIdx.x, lane = t & 31, wid = t >> 5;
    const int bh = blockIdx.y;

    {
        const float4* src = g_q4 + bh * 4224;
        for (int f = t; f < 4224; f += 512) q4[f] = src[f];
        for (int f = t; f < 1088; f += 512)
            *(float4*)(sv + 4 * f) = *(const float4*)(g_sv + bh * 4352 + 4 * f);
        for (int f = t; f < 1024; f += 512)
            *(float4*)(xsh + 4 * f) = *(const float4*)(g_xs + bh * 4096 + 4 * f);
    }
    __syncthreads();

    const int i = blockIdx.x * 16 + wid;
    const float u  = xsh[i * 32 + lane];
    const float u2 = 0.5f * u * u;
    const float u3 = u * u * u * (1.f / 6.f);

    float srow[4];
    #pragma unroll
    for (int b = 0; b < 4; ++b) {
        float cur[32];
        #pragma unroll
        for (int jj = 0; jj < 32; ++jj) {
            const int j = b * 32 + jj;
            const float* svj = sv + j * 34;
            int r = (svj[15] < u) ? 16 : 0;
            r += (svj[r + 7] < u) ? 8 : 0;
            r += (svj[r + 3] < u) ? 4 : 0;
            r += (svj[r + 1] < u) ? 2 : 0;
            const float2 pr = *(const float2*)(svj + r);   // r even, 8B aligned
            r += (pr.x < u) ? 1 : 0;
            r += (pr.y < u) ? 1 : 0;
            const float4 q = q4[j * 33 + r];
            cur[jj] = fmaf(u2, q.x, fmaf(u, q.y, fmaf(u3, q.w, q.z)));
        }
        // butterfly transpose-reduce: lane l ends with sum over lanes for j=b*32+l
        #pragma unroll
        for (int o = 16; o > 0; o >>= 1) {
            #pragma unroll
            for (int k = 0; k < o; ++k) {
                const float keep = (lane & o) ? cur[k + o] : cur[k];
                const float give = (lane & o) ? cur[k] : cur[k + o];
                const float got = __shfl_xor_sync(0xffffffffu, give, o);
                cur[k] = keep + got;
            }
        }
        srow[b] = cur[0];
    }

    // softmax over the 128 distributed logits (lane holds j = b*32+lane)
    const float l0 = srow[0] * (1.f / 32.f), l1 = srow[1] * (1.f / 32.f);
    const float l2 = srow[2] * (1.f / 32.f), l3 = srow[3] * (1.f / 32.f);
    float mx = fmaxf(fmaxf(l0, l1), fmaxf(l2, l3));
    mx = wmax(mx);
    const float e0 = __expf(l0 - mx), e1 = __expf(l1 - mx);
    const float e2 = __expf(l2 - mx), e3 = __expf(l3 - mx);
    float s = (e0 + e1) + (e2 + e3);
    s = wsum(s);
    const float inv = 1.f / s;
    float* at = attn + wid * 128;
    at[0 * 32 + lane] = e0 * inv;
    at[1 * 32 + lane] = e1 * inv;
    at[2 * 32 + lane] = e2 * inv;
    at[3 * 32 + lane] = e3 * inv;
    __syncwarp();

    // out[i, e] = sum_j attn[j] * x[j, e]
    float a0 = 0.f, a1 = 0.f;
    #pragma unroll 8
    for (int j = 0; j < 128; j += 2) {
        a0 = fmaf(at[j],     xsh[j * 32 + lane],       a0);
        a1 = fmaf(at[j + 1], xsh[(j + 1) * 32 + lane], a1);
    }
    g_o[(bh * 128 + i) * 32 + lane] = a0 + a1;
}

// ---------------------------------------------------------------------------
// K3: out = o @ w_out^T + b_out. 8-row tiles, K-split x2. grid(32,8), 256 thr.
// ---------------------------------------------------------------------------
__global__ void k_out(const float* __restrict__ w_out,
                      const float* __restrict__ b_out,
                      float* __restrict__ out) {
    extern __shared__ float sm[];
    float* xs = sm;
    float* ws = sm + 8 * 256;
    float* ps = ws + 32 * 257;

    const int t = threadIdx.x, lane = t & 31, wid = t >> 5;
    const int r0 = blockIdx.x * 8, c0 = blockIdx.y * 32;

    #pragma unroll
    for (int f = t; f < 512; f += 256) {
        const int r = f >> 6, kq = f & 63;
        const int row = r0 + r, b = row >> 7, s = row & 127;
        const int d = kq * 4, h = d >> 5, e = d & 31;
        *(float4*)(xs + r * 256 + kq * 4) =
            *(const float4*)(g_o + ((b * 8 + h) * 128 + s) * 32 + e);
    }
    #pragma unroll
    for (int rr = 0; rr < 4; ++rr) {
        const int cc = wid * 4 + rr;
        #pragma unroll
        for (int hh = 0; hh < 2; ++hh) {
            const int k4 = hh * 32 + lane;
            const float4 v = *(const float4*)(w_out + (c0 + cc) * 256 + k4 * 4);
            float* d = ws + cc * 257 + k4 * 4;
            d[0] = v.x; d[1] = v.y; d[2] = v.z; d[3] = v.w;
        }
    }
    __syncthreads();

    const int kh = wid >> 2, rg = wid & 3;
    const float* wrow = ws + lane * 257 + kh * 128;
    float acc[2] = {0.f, 0.f};
    #pragma unroll 8
    for (int kq = 0; kq < 32; ++kq) {
        const float w0 = wrow[4 * kq + 0], w1 = wrow[4 * kq + 1];
        const float w2 = wrow[4 * kq + 2], w3 = wrow[4 * kq + 3];
        #pragma unroll
        for (int rr = 0; rr < 2; ++rr) {
            const float4 x4 = *(const float4*)(xs + (rg * 2 + rr) * 256 + kh * 128 + 4 * kq);
            acc[rr] = fmaf(w0, x4.x, fmaf(w1, x4.y, fmaf(w2, x4.z, fmaf(w3, x4.w, acc[rr]))));
        }
    }
    if (kh == 1) {
        #pragma unroll
        for (int rr = 0; rr < 2; ++rr) ps[(rg * 2 + rr) * 32 + lane] = acc[rr];
    }
    __syncthreads();
    if (kh == 0) {
        const float bb = b_out[c0 + lane];
        #pragma unroll
        for (int rr = 0; rr < 2; ++rr)
            out[(r0 + rg * 2 + rr) * 256 + c0 + lane] =
                acc[rr] + ps[(rg * 2 + rr) * 32 + lane] + bb;
    }
}

extern "C" void kernel_launch(void* const* d_in, const int* in_sizes, int n_in,
                              void* d_out, int out_size) {
    const float* inp   = (const float*)d_in[0];
    const float* w_in  = (const float*)d_in[1];
    const float* b_in  = (const float*)d_in[2];
    const float* w_out = (const float*)d_in[3];
    const float* b_out = (const float*)d_in[4];
    float* out = (float*)d_out;
    (void)in_sizes; (void)n_in; (void)out_size;

    cudaFuncSetAttribute(k_proj,   cudaFuncAttributeMaxDynamicSharedMemorySize, SMEM_PROJ);
    cudaFuncSetAttribute(k_spline, cudaFuncAttributeMaxDynamicSharedMemorySize, SMEM_SPL);
    cudaFuncSetAttribute(k_out,    cudaFuncAttributeMaxDynamicSharedMemorySize, SMEM_OUT);

    k_proj  <<<dim3(32, 8), 256, SMEM_PROJ>>>(inp, w_in, b_in);
    k_spline<<<dim3(8, 16), 512, SMEM_SPL>>>();
    k_out   <<<dim3(32, 8), 256, SMEM_OUT>>>(w_out, b_out, out);
}